// round 16
// baseline (speedup 1.0000x reference)
#include <cuda_runtime.h>
#include <cuda_bf16.h>
#include <math.h>

// Dimensions (fixed by the problem)
#define B_ROWS 512
#define D_IN 5
#define H_DIM 128
#define VF_DIM 256
#define L_SEG 62        // LS-1
#define LAB 10
#define NSTEP 20
#define RB 8            // rows per CLUSTER (2 CTAs)
#define NCTA 128
#define NTHR 512

typedef unsigned long long ull_t;

// Packed weight layouts (device globals; setup kernel fills them).
// Column-halved per cluster rank. k interleaved over 8 in-warp slices.
//   W1p[half][16384]: flat = i*1024 + w*64 + kq*8 + cgl*2 + cc
//       k = i*8+kq (i<16), col c = half*128 + w*8 + cgl*2 + cc
//   W2p[half][32768]: same with i<32 (K=256)
//   Wmp[kt][half][16384]: flat = i*512 + w*32 + kq*4 + cgl
//       k = i*8+kq (i<32), h = half*64 + w*4 + cgl
__device__ float g_W1p[2 * 16384];
__device__ float g_W2p[2 * 32768];
__device__ float g_Wmp[32 * 32768];              // 4 MB
__device__ float g_bm[32 * H_DIM];               // [kt][h]
__device__ float g_delta[32];
__device__ int   g_idx[2 * NSTEP];

// ---------------------------------------------------------------------------
// f32x2 + shuffle helpers (sm_103a FFMA2/FADD2 — PTX-only)
// ---------------------------------------------------------------------------
__device__ __forceinline__ ull_t dup2(float x) {
    ull_t r; unsigned int u = __float_as_uint(x);
    asm("mov.b64 %0, {%1, %1};" : "=l"(r) : "r"(u));
    return r;
}
__device__ __forceinline__ ull_t pk2(float a, float b) {
    ull_t r;
    asm("mov.b64 %0, {%1, %2};" : "=l"(r) : "r"(__float_as_uint(a)), "r"(__float_as_uint(b)));
    return r;
}
__device__ __forceinline__ void fma2(ull_t& acc, ull_t a, ull_t b) {
    asm("fma.rn.f32x2 %0, %1, %2, %0;" : "+l"(acc) : "l"(a), "l"(b));
}
__device__ __forceinline__ ull_t add2(ull_t a, ull_t b) {
    ull_t r;
    asm("add.rn.f32x2 %0, %1, %2;" : "=l"(r) : "l"(a), "l"(b));
    return r;
}
__device__ __forceinline__ void unpk(ull_t v, float& a, float& b) {
    unsigned int lo, hi;
    asm("mov.b64 {%0, %1}, %2;" : "=r"(lo), "=r"(hi) : "l"(v));
    a = __uint_as_float(lo); b = __uint_as_float(hi);
}
__device__ __forceinline__ ull_t shfl_xor64(ull_t v, int m) {
    unsigned int lo, hi;
    asm("mov.b64 {%0, %1}, %2;" : "=r"(lo), "=r"(hi) : "l"(v));
    lo = __shfl_xor_sync(0xffffffffu, lo, m);
    hi = __shfl_xor_sync(0xffffffffu, hi, m);
    ull_t r;
    asm("mov.b64 %0, {%1, %2};" : "=l"(r) : "r"(lo), "r"(hi));
    return r;
}
__device__ __forceinline__ unsigned int su32(const void* p) {
    unsigned int r;
    asm("{ .reg .u64 t; cvta.to.shared.u64 t, %1; cvt.u32.u64 %0, t; }" : "=r"(r) : "l"(p));
    return r;
}
__device__ __forceinline__ unsigned int mapa_u32(unsigned int addr, unsigned int rank) {
    unsigned int r;
    asm("mapa.shared::cluster.u32 %0, %1, %2;" : "=r"(r) : "r"(addr), "r"(rank));
    return r;
}
__device__ __forceinline__ void st_async64(unsigned int raddr, ull_t v, unsigned int rmbar) {
    asm volatile("st.async.shared::cluster.mbarrier::complete_tx::bytes.b64 [%0], %1, [%2];"
                 :: "r"(raddr), "l"(v), "r"(rmbar) : "memory");
}
__device__ __forceinline__ void st_async32(unsigned int raddr, float v, unsigned int rmbar) {
    asm volatile("st.async.shared::cluster.mbarrier::complete_tx::bytes.b32 [%0], %1, [%2];"
                 :: "r"(raddr), "r"(__float_as_uint(v)), "r"(rmbar) : "memory");
}
#define MBAR_INIT(a, n) \
    asm volatile("mbarrier.init.shared.b64 [%0], %1;" :: "r"(a), "r"((unsigned)(n)) : "memory")
#define MBAR_ARRIVE(a) \
    asm volatile("mbarrier.arrive.shared.b64 _, [%0];" :: "r"(a) : "memory")
#define MBAR_ARRIVE_EXPECT(a, tx) \
    asm volatile("mbarrier.arrive.expect_tx.shared.b64 _, [%0], %1;" :: "r"(a), "r"((unsigned)(tx)) : "memory")
#define MBAR_WAIT(a, par) do { \
    unsigned _m = (a), _p = (par), _d; \
    asm volatile("{\n\t.reg .pred p;\n\t" \
        "mbarrier.try_wait.parity.acquire.cta.shared::cta.b64 p, [%1], %2;\n\t" \
        "selp.b32 %0, 1, 0, p;\n\t}" : "=r"(_d) : "r"(_m), "r"(_p) : "memory"); \
    if (!_d) { \
        asm volatile("{\n\t.reg .pred P1;\n\t" \
            "WL_%=:\n\t" \
            "mbarrier.try_wait.parity.acquire.cta.shared::cta.b64 P1, [%0], %1, 0x989680;\n\t" \
            "@P1 bra.uni WD_%=;\n\t" \
            "bra.uni WL_%=;\n\t" \
            "WD_%=:\n\t}" :: "r"(_m), "r"(_p) : "memory"); \
    } \
} while (0)
#define CLUSTER_SYNC_() do { \
    asm volatile("barrier.cluster.arrive.aligned;" ::: "memory"); \
    asm volatile("barrier.cluster.wait.aligned;" ::: "memory"); \
} while (0)

// ---------------------------------------------------------------------------
// Setup kernel.  grid = 160 x 256.  All fp32, packed layouts.
// ---------------------------------------------------------------------------
__global__ void __launch_bounds__(256) setup_kernel(
    const float* __restrict__ ts,
    const float* __restrict__ intervals,
    const float* __restrict__ W1,      // [256][128]
    const float* __restrict__ W2,      // [256][256]
    const float* __restrict__ logsig,  // [32][63]
    const float* __restrict__ Wm,      // [7936][256]
    const float* __restrict__ bm)      // [7936]
{
    if (blockIdx.x < 128) {
        __shared__ float ls[32 * L_SEG];
        int h = blockIdx.x;                    // output col 0..127
        int v = threadIdx.x;                   // k 0..255

        for (int i = threadIdx.x; i < 32 * L_SEG; i += blockDim.x) {
            int row = i / L_SEG, l = i % L_SEG;
            ls[i] = logsig[row * 63 + l + 1];
        }
        __syncthreads();

        float acc[32];
        #pragma unroll
        for (int i = 0; i < 32; i++) acc[i] = 0.0f;

        for (int l = 0; l < L_SEG; l++) {
            float w = __ldg(&Wm[(h * L_SEG + l) * VF_DIM + v]);
            #pragma unroll
            for (int i = 0; i < 32; i++) acc[i] += w * ls[i * L_SEG + l];
        }
        // dst: half = h>>6, w = (h&63)>>2, cgl = h&3, i = v>>3, kq = v&7
        int dst = (h >> 6) * 16384 + (v >> 3) * 512 + ((h & 63) >> 2) * 32
                + (v & 7) * 4 + (h & 3);
        #pragma unroll
        for (int i = 0; i < 32; i++)
            g_Wmp[i * 32768 + dst] = acc[i];

        if (threadIdx.x < 32) {
            int i = threadIdx.x;
            float s = 0.0f;
            for (int l = 0; l < L_SEG; l++)
                s += __ldg(&bm[h * L_SEG + l]) * ls[i * L_SEG + l];
            g_bm[i * H_DIM + h] = s;
        }
    } else {
        int b = blockIdx.x - 128;              // 0..31
        int gtid = b * 256 + threadIdx.x;      // 0..8191
        int gsz  = 32 * 256;

        for (int i = gtid; i < H_DIM * VF_DIM; i += gsz) {
            int k = i >> 8, c = i & 255;
            int cl = c & 127;
            int d = (c >> 7) * 16384 + (k >> 3) * 1024 + (cl >> 3) * 64
                  + (k & 7) * 8 + ((cl & 7) >> 1) * 2 + (cl & 1);
            g_W1p[d] = W1[c * H_DIM + k];
        }
        for (int i = gtid; i < VF_DIM * VF_DIM; i += gsz) {
            int k = i >> 8, c = i & 255;
            int cl = c & 127;
            int d = (c >> 7) * 32768 + (k >> 3) * 1024 + (cl >> 3) * 64
                  + (k & 7) * 8 + ((cl & 7) >> 1) * 2 + (cl & 1);
            g_W2p[d] = W2[c * VF_DIM + k];
        }
        if (b == 0) {
            if (threadIdx.x < 32)
                g_delta[threadIdx.x] = intervals[threadIdx.x + 1] - intervals[threadIdx.x];
            if (threadIdx.x < 2 * NSTEP) {
                // Replicate reference fp32 exactly
                float t0 = ts[0];
                float dt = (ts[32] - t0) / 20.0f;
                int i = threadIdx.x >> 1;
                float t = t0 + (float)i * dt;
                if (threadIdx.x & 1) t = t + dt;
                int cnt = 0;
                #pragma unroll
                for (int j = 1; j <= 32; j++) cnt += (intervals[j] < t) ? 1 : 0;
                int idx = cnt + 1;
                idx = max(1, min(idx, 32));
                g_idx[threadIdx.x] = idx - 1;
            }
        }
    }
}

// One k-iter (2 cols x 8 rows): float2 weight, acts 2x ull2, 8 FFMA2.
__device__ __forceinline__ void mac28(float2 w, const float* ap, ull_t acc[2][4])
{
    ulonglong2 a0 = *(const ulonglong2*)ap;        // rows 0..3
    ulonglong2 a1 = *(const ulonglong2*)(ap + 4);  // rows 4..7
    ull_t d;
    d = dup2(w.x);
    fma2(acc[0][0], d, a0.x); fma2(acc[0][1], d, a0.y);
    fma2(acc[0][2], d, a1.x); fma2(acc[0][3], d, a1.y);
    d = dup2(w.y);
    fma2(acc[1][0], d, a0.x); fma2(acc[1][1], d, a0.y);
    fma2(acc[1][2], d, a1.x); fma2(acc[1][3], d, a1.y);
}

// Reduce-scatter over 8 in-warp K-slices: acc[2][4] -> 1 f32x2 per lane.
// Final slot: cc = (l>>4)&1, rp = ((l>>3)&1)*2 + ((l>>2)&1).
__device__ __forceinline__ ull_t rs8c(ull_t acc[2][4], int l)
{
    bool b16 = (l & 16);
    #pragma unroll
    for (int rp = 0; rp < 4; rp++) {
        ull_t snd = b16 ? acc[0][rp] : acc[1][rp];
        ull_t kp  = b16 ? acc[1][rp] : acc[0][rp];
        acc[0][rp] = add2(kp, shfl_xor64(snd, 16));
    }
    bool b8 = (l & 8);
    #pragma unroll
    for (int j = 0; j < 2; j++) {
        ull_t snd = b8 ? acc[0][j] : acc[0][j + 2];
        ull_t kp  = b8 ? acc[0][j + 2] : acc[0][j];
        acc[0][j] = add2(kp, shfl_xor64(snd, 8));
    }
    bool b4 = (l & 4);
    ull_t snd = b4 ? acc[0][0] : acc[0][1];
    ull_t kp  = b4 ? acc[0][1] : acc[0][0];
    return add2(kp, shfl_xor64(snd, 4));
}

// Reduce-scatter L3: m[4] (rowpairs) -> 1 scalar.
// Final slot: r = ((l>>4)&1)*4 + ((l>>3)&1)*2 + ((l>>2)&1).
__device__ __forceinline__ float rs4c(ull_t m[4], int l)
{
    bool b16 = (l & 16);
    #pragma unroll
    for (int j = 0; j < 2; j++) {
        ull_t snd = b16 ? m[j] : m[j + 2];
        ull_t kp  = b16 ? m[j + 2] : m[j];
        m[j] = add2(kp, shfl_xor64(snd, 16));
    }
    bool b8 = (l & 8);
    ull_t snd = b8 ? m[0] : m[1];
    ull_t kp  = b8 ? m[1] : m[0];
    ull_t f2 = add2(kp, shfl_xor64(snd, 8));
    float f0, f1;
    unpk(f2, f0, f1);
    bool b4 = (l & 4);
    float snf = b4 ? f0 : f1;
    float kpf = b4 ? f1 : f0;
    return kpf + __shfl_xor_sync(0xffffffffu, snf, 4);
}

// ---------------------------------------------------------------------------
// Persistent integration kernel: 128 CTAs, cluster(2): 8 rows per cluster.
// Each CTA owns half the output columns of every layer (full K) with
// W1-half + W2-half permanently smem-resident; Wm-half streamed per eval.
// Act halves exchanged via st.async DSMEM + mbarrier complete_tx.
// ---------------------------------------------------------------------------
// smem floats: W1s 16384 | W2s 32768 | y 1024 | yt 1024 | h1 2048 | h2 2048
//            | b1 256 | b2 256 | dl 32 | idx 40 | mbars 6
#define SMEM_FLOATS (16384 + 32768 + 1024 + 1024 + 2048 + 2048 + 256 + 256 + 32 + 40 + 6)

__global__ void __launch_bounds__(NTHR, 1) __cluster_dims__(2, 1, 1)
integrate_kernel(const float* __restrict__ x0,     // [512][5]
                 const float* __restrict__ W_in,   // [128][5]
                 const float* __restrict__ b_in,   // [128]
                 const float* __restrict__ b1,     // [256]
                 const float* __restrict__ b2,     // [256]
                 const float* __restrict__ W_out,  // [10][128]
                 const float* __restrict__ b_out,  // [10]
                 const float* __restrict__ ts,
                 float* __restrict__ out)          // [512][10]
{
    extern __shared__ __align__(16) float sm[];
    float* W1s  = sm;                    // 16384 (64 KB, resident)
    float* W2s  = W1s + 16384;           // 32768 (128 KB, resident)
    float* y_s  = W2s + 32768;           // 1024 : y  [h=128][r=8]
    float* yt_s = y_s + 1024;            // 1024
    float* h1_s = yt_s + 1024;           // 2048 : [c=256][r=8]
    float* h2_s = h1_s + 2048;           // 2048
    float* b1_s = h2_s + 2048;           // 256
    float* b2_s = b1_s + 256;            // 256
    float* dl_s = b2_s + 256;            // 32
    int*   idx_s = (int*)(dl_s + 32);    // 40
    float* mbf  = dl_s + 32 + 40;        // 6 floats = 3 x u64 mbarriers

    const int tid = threadIdx.x;
    unsigned int rank;
    asm("mov.u32 %0, %%cluster_ctarank;" : "=r"(rank));
    const unsigned int peer = rank ^ 1u;
    const int r0  = (blockIdx.x >> 1) * RB;      // cluster row base

    const int w   = tid >> 5;            // warp 0..15
    const int l   = tid & 31;
    const int kq  = l >> 2;              // K-slice 0..7
    const int cgl = l & 3;

    // Final slots
    const int cc12 = (l >> 4) & 1;
    const int rp12 = ((l >> 3) & 1) * 2 + ((l >> 2) & 1);
    const int c12  = (int)rank * 128 + w * 8 + cgl * 2 + cc12;   // L1/L2 col
    const int h3   = (int)rank * 64 + w * 4 + cgl;               // L3 col
    const int r3   = ((l >> 4) & 1) * 4 + ((l >> 3) & 1) * 2 + ((l >> 2) & 1);

    // Lane weight bases
    const float* wl1 = W1s + w * 64 + kq * 8 + cgl * 2;
    const float* wl2 = W2s + w * 64 + kq * 8 + cgl * 2;
    const int wmoff  = (int)rank * 16384 + w * 32 + kq * 4 + cgl;
    const int abase  = kq * 8;           // act float offset per iter: + i*64

    // Fill resident weights (own half only)
    for (int i = tid; i < 4096; i += NTHR)
        *(float4*)&W1s[i * 4] = *(const float4*)&g_W1p[rank * 16384 + i * 4];
    for (int i = tid; i < 8192; i += NTHR)
        *(float4*)&W2s[i * 4] = *(const float4*)&g_W2p[rank * 32768 + i * 4];
    if (tid < 256) { b1_s[tid] = b1[tid]; b2_s[tid] = b2[tid]; }
    if (tid < 32)  dl_s[tid] = g_delta[tid];
    if (tid < 2 * NSTEP) idx_s[tid] = g_idx[tid];

    // y0 = x0 @ W_in^T + b_in : both CTAs compute full [128h][8r] identically
    #pragma unroll
    for (int q = 0; q < 2; q++) {
        int idx = q * NTHR + tid;        // 0..1023
        int h = idx >> 3, r = idx & 7;
        float acc = __ldg(&b_in[h]);
        #pragma unroll
        for (int d = 0; d < D_IN; d++)
            acc += __ldg(&x0[(r0 + r) * D_IN + d]) * __ldg(&W_in[h * D_IN + d]);
        y_s[idx] = acc;
    }
    const float dt = (ts[32] - ts[0]) / 20.0f;

    // mbarriers: count = 513 (512 data arrivals + 1 expect-arrive)
    unsigned int mb[3];
    mb[0] = su32(mbf); mb[1] = mb[0] + 8; mb[2] = mb[0] + 16;
    if (tid == 0) {
        MBAR_INIT(mb[0], 513);
        MBAR_INIT(mb[1], 513);
        MBAR_INIT(mb[2], 513);
        // fence so peer sees initialized barriers after cluster sync
        asm volatile("fence.mbarrier_init.release.cluster;" ::: "memory");
    }
    __syncthreads();
    if (tid == 0) {
        MBAR_ARRIVE_EXPECT(mb[0], 4096);
        MBAR_ARRIVE_EXPECT(mb[1], 4096);
        MBAR_ARRIVE_EXPECT(mb[2], 2048);
    }
    CLUSTER_SYNC_();

    // Remote addresses (peer CTA)
    const unsigned int rmb0 = mapa_u32(mb[0], peer);
    const unsigned int rmb1 = mapa_u32(mb[1], peer);
    const unsigned int rmb2 = mapa_u32(mb[2], peer);
    const unsigned int l_h1 = su32(h1_s) + (unsigned)(c12 * 8 + rp12 * 2) * 4;
    const unsigned int l_h2 = su32(h2_s) + (unsigned)(c12 * 8 + rp12 * 2) * 4;
    const unsigned int l_y  = su32(y_s)  + (unsigned)(h3 * 8 + r3) * 4;
    const unsigned int l_yt = su32(yt_s) + (unsigned)(h3 * 8 + r3) * 4;
    const unsigned int r_h1 = mapa_u32(l_h1, peer);
    const unsigned int r_h2 = mapa_u32(l_h2, peer);
    const unsigned int r_y  = mapa_u32(l_y,  peer);
    const unsigned int r_yt = mapa_u32(l_yt, peer);

    // Rolling Wm pipeline (depth 4, cross-eval wrap)
    float wmbuf[4];
    {
        const float* p0 = g_Wmp + idx_s[0] * 32768 + wmoff;
        #pragma unroll
        for (int j = 0; j < 4; j++) wmbuf[j] = __ldg(p0 + j * 512);
    }

    float k1r = 0.0f;

    for (int step = 0; step < NSTEP; step++) {
        #pragma unroll 1
        for (int phase = 0; phase < 2; phase++) {
            const float* in_s = phase ? yt_s : y_s;
            const int e  = 2 * step + phase;
            const unsigned par = (unsigned)(e & 1);
            const int kt = idx_s[e];
            const int en = (e + 1 < 2 * NSTEP) ? e + 1 : e;
            const float* wmc = g_Wmp + kt * 32768 + wmoff;
            const float* wmn = g_Wmp + idx_s[en] * 32768 + wmoff;
            const float bmv = __ldg(&g_bm[kt * H_DIM + h3]);
            const float dl  = dl_s[kt];

            // ==== Layer 1: K=128, 16 iters (resident smem weights) ====
            {
                ull_t acc[2][4];
                #pragma unroll
                for (int j = 0; j < 4; j++) { acc[0][j] = 0ull; acc[1][j] = 0ull; }
                #pragma unroll
                for (int i = 0; i < 16; i++) {
                    float2 wv = *(const float2*)(wl1 + i * 1024);
                    mac28(wv, in_s + i * 64 + abase, acc);
                }
                ull_t fin = rs8c(acc, l);
                float v0, v1;
                unpk(fin, v0, v1);
                float bb = b1_s[c12];
                v0 = fmaxf(v0 + bb, 0.f); v1 = fmaxf(v1 + bb, 0.f);
                *(float2*)&h1_s[c12 * 8 + rp12 * 2] = make_float2(v0, v1);
                st_async64(r_h1, pk2(v0, v1), rmb0);
                MBAR_ARRIVE(mb[0]);
            }
            MBAR_WAIT(mb[0], par);
            if (tid == 0) MBAR_ARRIVE_EXPECT(mb[0], 4096);   // re-arm next use

            // ==== Layer 2: K=256, 32 iters (resident smem weights) ====
            {
                ull_t acc[2][4];
                #pragma unroll
                for (int j = 0; j < 4; j++) { acc[0][j] = 0ull; acc[1][j] = 0ull; }
                #pragma unroll
                for (int i = 0; i < 32; i++) {
                    float2 wv = *(const float2*)(wl2 + i * 1024);
                    mac28(wv, h1_s + i * 64 + abase, acc);
                }
                ull_t fin = rs8c(acc, l);
                float v0, v1;
                unpk(fin, v0, v1);
                float bb = b2_s[c12];
                v0 = tanhf(v0 + bb); v1 = tanhf(v1 + bb);
                *(float2*)&h2_s[c12 * 8 + rp12 * 2] = make_float2(v0, v1);
                st_async64(r_h2, pk2(v0, v1), rmb1);
                MBAR_ARRIVE(mb[1]);
            }
            MBAR_WAIT(mb[1], par);
            if (tid == 0) MBAR_ARRIVE_EXPECT(mb[1], 4096);

            // ==== Layer 3: K=256, 32 iters, rolling global Wm + Heun ====
            {
                ull_t m[4];
                m[0] = 0ull; m[1] = 0ull; m[2] = 0ull; m[3] = 0ull;
                #pragma unroll
                for (int i = 0; i < 32; i++) {
                    float wv = wmbuf[i & 3];
                    if (i + 4 < 32)
                        wmbuf[i & 3] = __ldg(wmc + (i + 4) * 512);
                    else
                        wmbuf[i & 3] = __ldg(wmn + (i + 4 - 32) * 512);
                    const float* ap = h2_s + i * 64 + abase;
                    ulonglong2 a0 = *(const ulonglong2*)ap;
                    ulonglong2 a1 = *(const ulonglong2*)(ap + 4);
                    ull_t d = dup2(wv);
                    fma2(m[0], d, a0.x); fma2(m[1], d, a0.y);
                    fma2(m[2], d, a1.x); fma2(m[3], d, a1.y);
                }
                float a = rs4c(m, l);
                float d = (a + bmv) / dl;
                int addr = h3 * 8 + r3;
                if (phase == 0) {
                    k1r = d;
                    float nv = y_s[addr] + dt * d;
                    yt_s[addr] = nv;
                    st_async32(r_yt, nv, rmb2);
                } else {
                    float nv = y_s[addr] + 0.5f * dt * (k1r + d);
                    y_s[addr] = nv;
                    st_async32(r_y, nv, rmb2);
                }
                MBAR_ARRIVE(mb[2]);
            }
            MBAR_WAIT(mb[2], par);
            if (tid == 0) MBAR_ARRIVE_EXPECT(mb[2], 2048);
        }
    }

    // ---- Output: softmax over this CTA's 4 rows (rank-split of 8) ----
    if (tid < 4 * LAB) {
        int lab = tid % LAB, r = tid / LAB;          // r 0..3
        int rin = (int)rank * 4 + r;                 // row within cluster
        float acc = __ldg(&b_out[lab]);
        for (int k = 0; k < H_DIM; k++)
            acc += y_s[k * 8 + rin] * __ldg(&W_out[lab * H_DIM + k]);
        h1_s[r * LAB + lab] = acc;
    }
    __syncthreads();
    if (tid < 4) {
        int r = tid;
        float mx = -1e30f;
        #pragma unroll
        for (int q = 0; q < LAB; q++) mx = fmaxf(mx, h1_s[r * LAB + q]);
        float e[LAB]; float sum = 0.f;
        #pragma unroll
        for (int q = 0; q < LAB; q++) { e[q] = expf(h1_s[r * LAB + q] - mx); sum += e[q]; }
        int orow = r0 + (int)rank * 4 + r;
        #pragma unroll
        for (int q = 0; q < LAB; q++) out[orow * LAB + q] = e[q] / sum;
    }

    CLUSTER_SYNC_();   // keep cluster smem alive until all traffic done
}

// ---------------------------------------------------------------------------
extern "C" void kernel_launch(void* const* d_in, const int* in_sizes, int n_in,
                              void* d_out, int out_size)
{
    const float* ts        = (const float*)d_in[0];
    const float* logsig    = (const float*)d_in[1];
    const float* x0        = (const float*)d_in[2];
    const float* intervals = (const float*)d_in[3];
    const float* W_vf1     = (const float*)d_in[4];
    const float* b_vf1     = (const float*)d_in[5];
    const float* W_vf2     = (const float*)d_in[6];
    const float* b_vf2     = (const float*)d_in[7];
    const float* W_m       = (const float*)d_in[8];
    const float* b_m       = (const float*)d_in[9];
    const float* W_in      = (const float*)d_in[10];
    const float* b_in      = (const float*)d_in[11];
    const float* W_out     = (const float*)d_in[12];
    const float* b_out     = (const float*)d_in[13];
    float* out = (float*)d_out;

    size_t smem_bytes = SMEM_FLOATS * sizeof(float);  // 223,544 B
    cudaFuncSetAttribute(integrate_kernel,
                         cudaFuncAttributeMaxDynamicSharedMemorySize,
                         (int)smem_bytes);

    setup_kernel<<<160, 256>>>(ts, intervals, W_vf1, W_vf2, logsig, W_m, b_m);
    integrate_kernel<<<NCTA, NTHR, smem_bytes>>>(x0, W_in, b_in, b_vf1, b_vf2,
                                                 W_out, b_out, ts, out);
}